// round 4
// baseline (speedup 1.0000x reference)
#include <cuda_runtime.h>
#include <cuda_bf16.h>
#include <cstdint>

// ---------------------------------------------------------------------------
// VectorQuantize: z [32768,512] f32, codebook [8192,512] f32
// Reference semantics replicated exactly:
//   p    = z @ cb.T                       (fp32 accum)
//   dist = fl( fl(r_m + c_n) - 2*p )      (fp32, ULP(~512) grid => ties!)
//   idx  = argmin dist, first index on ties
//   out  = concat( z + fl(q - z) [N*512], idx as f32 [N], 1.25*mean((z-q)^2) )
// ---------------------------------------------------------------------------

#define NTOK_MAX 32768
#define KCB_MAX  8192

__device__ unsigned long long g_bestkey[NTOK_MAX];
__device__ float              g_codenorm[KCB_MAX];   // ||e_n||^2
__device__ float              g_zn[NTOK_MAX];        // ||z_m||^2
__device__ float              g_tokensum[NTOK_MAX];

// ---- packed f32x2 helpers --------------------------------------------------
__device__ __forceinline__ unsigned long long dup2(float x) {
    unsigned long long d;
    asm("mov.b64 %0, {%1, %1};" : "=l"(d) : "f"(x));
    return d;
}
__device__ __forceinline__ void fma2(unsigned long long& acc,
                                     unsigned long long a,
                                     unsigned long long b) {
    asm("fma.rn.f32x2 %0, %1, %2, %0;" : "+l"(acc) : "l"(a), "l"(b));
}
__device__ __forceinline__ void unpack2(unsigned long long v, float& lo, float& hi) {
    asm("mov.b64 {%0, %1}, %2;" : "=f"(lo), "=f"(hi) : "l"(v));
}
// order-preserving float -> uint map (monotone increasing)
__device__ __forceinline__ unsigned ordf(float f) {
    unsigned u = __float_as_uint(f);
    return (u & 0x80000000u) ? ~u : (u | 0x80000000u);
}

// ---------------------------------------------------------------------------
__global__ void vq_init_kernel(int ntok) {
    int i = blockIdx.x * blockDim.x + threadIdx.x;
    if (i < ntok) g_bestkey[i] = 0ull;
}

// row norm ||v||^2 into a __device__ global selected by `dest`
// (device globals must NOT be passed as kernel args from host code).
__global__ void vq_rownorm_kernel(const float* __restrict__ X, int dest) {
    int c = blockIdx.x;
    int t = threadIdx.x;
    float4 v = reinterpret_cast<const float4*>(X + (size_t)c * 512)[t];
    float s = v.x * v.x + v.y * v.y + v.z * v.z + v.w * v.w;
    #pragma unroll
    for (int off = 16; off; off >>= 1)
        s += __shfl_xor_sync(0xFFFFFFFFu, s, off);
    __shared__ float ws[4];
    if ((t & 31) == 0) ws[t >> 5] = s;
    __syncthreads();
    if (t == 0) {
        float r = ws[0] + ws[1] + ws[2] + ws[3];
        if (dest == 0) g_codenorm[c] = r;
        else           g_zn[c] = r;
    }
}

// ---------------------------------------------------------------------------
// Fused fp32 GEMM: 128x128 CTA tile, BK=16, 128 threads, 16x8 per-thread tile
// via f32x2 FMA. LDS per MAC cut 25% vs 8x8 (l1tex was the binding pipe).
// + reference-exact dist rounding + argmin(first-index ties) publish.
// ---------------------------------------------------------------------------
#define BM 128
#define BN 128
#define BK 16
#define TS 132   // padded row stride (floats)

__global__ __launch_bounds__(128, 2)
void vq_gemm_kernel(const float* __restrict__ Z, const float* __restrict__ CB,
                    int kcb) {
    __shared__ float As[2][BK * TS];   // [k][m]
    __shared__ float Bs[2][BK * TS];   // [k][n]

    const int tid = threadIdx.x;
    const int tx = tid & 15;      // n-thread: 16 x 8 cols = 128
    const int ty = tid >> 4;      // m-thread: 8 x 16 rows = 128
    const int mBase = blockIdx.y * BM;
    const int nBase = blockIdx.x * BN;

    // global loaders: thread tid owns full k-slab of row `tid` (A and B)
    const float* Ap = Z  + (size_t)(mBase + tid) * 512;
    const float* Bp = CB + (size_t)(nBase + tid) * 512;

    float4 ra[4], rb[4];
    #pragma unroll
    for (int j = 0; j < 4; ++j) {
        ra[j] = *reinterpret_cast<const float4*>(Ap + j * 4);
        rb[j] = *reinterpret_cast<const float4*>(Bp + j * 4);
    }

    unsigned long long acc[16][4];
    #pragma unroll
    for (int i = 0; i < 16; ++i)
        #pragma unroll
        for (int j = 0; j < 4; ++j) acc[i][j] = 0ull;

    // store first tile transposed
    #pragma unroll
    for (int j = 0; j < 4; ++j) {
        As[0][(j * 4 + 0) * TS + tid] = ra[j].x;
        As[0][(j * 4 + 1) * TS + tid] = ra[j].y;
        As[0][(j * 4 + 2) * TS + tid] = ra[j].z;
        As[0][(j * 4 + 3) * TS + tid] = ra[j].w;
        Bs[0][(j * 4 + 0) * TS + tid] = rb[j].x;
        Bs[0][(j * 4 + 1) * TS + tid] = rb[j].y;
        Bs[0][(j * 4 + 2) * TS + tid] = rb[j].z;
        Bs[0][(j * 4 + 3) * TS + tid] = rb[j].w;
    }
    __syncthreads();

    int buf = 0;
    const int NK = 512 / BK;  // 32
    for (int t = 0; t < NK; ++t) {
        if (t + 1 < NK) {
            Ap += BK; Bp += BK;
            #pragma unroll
            for (int j = 0; j < 4; ++j) {
                ra[j] = *reinterpret_cast<const float4*>(Ap + j * 4);
                rb[j] = *reinterpret_cast<const float4*>(Bp + j * 4);
            }
        }

        #pragma unroll
        for (int k = 0; k < BK; ++k) {
            const float* ap = &As[buf][k * TS + ty * 16];
            float4 av0 = *reinterpret_cast<const float4*>(ap);
            float4 av1 = *reinterpret_cast<const float4*>(ap + 4);
            float4 av2 = *reinterpret_cast<const float4*>(ap + 8);
            float4 av3 = *reinterpret_cast<const float4*>(ap + 12);
            const float* bp_ = &Bs[buf][k * TS + tx * 8];
            ulonglong2 bv0 = *reinterpret_cast<const ulonglong2*>(bp_);
            ulonglong2 bv1 = *reinterpret_cast<const ulonglong2*>(bp_ + 4);
            unsigned long long bp[4] = {bv0.x, bv0.y, bv1.x, bv1.y};
            float af[16] = {av0.x, av0.y, av0.z, av0.w,
                            av1.x, av1.y, av1.z, av1.w,
                            av2.x, av2.y, av2.z, av2.w,
                            av3.x, av3.y, av3.z, av3.w};
            #pragma unroll
            for (int i = 0; i < 16; ++i) {
                unsigned long long da = dup2(af[i]);
                fma2(acc[i][0], da, bp[0]);
                fma2(acc[i][1], da, bp[1]);
                fma2(acc[i][2], da, bp[2]);
                fma2(acc[i][3], da, bp[3]);
            }
        }

        if (t + 1 < NK) {
            int nb = buf ^ 1;
            #pragma unroll
            for (int j = 0; j < 4; ++j) {
                As[nb][(j * 4 + 0) * TS + tid] = ra[j].x;
                As[nb][(j * 4 + 1) * TS + tid] = ra[j].y;
                As[nb][(j * 4 + 2) * TS + tid] = ra[j].z;
                As[nb][(j * 4 + 3) * TS + tid] = ra[j].w;
                Bs[nb][(j * 4 + 0) * TS + tid] = rb[j].x;
                Bs[nb][(j * 4 + 1) * TS + tid] = rb[j].y;
                Bs[nb][(j * 4 + 2) * TS + tid] = rb[j].z;
                Bs[nb][(j * 4 + 3) * TS + tid] = rb[j].w;
            }
        }
        __syncthreads();
        buf ^= 1;
    }

    // ---- epilogue: reference-exact dist rounding, argmin, publish ---------
    float cn[8];
    #pragma unroll
    for (int j = 0; j < 8; ++j) cn[j] = g_codenorm[nBase + tx * 8 + j];

    #pragma unroll
    for (int i = 0; i < 16; ++i) {
        const float r = g_zn[mBase + ty * 16 + i];
        unsigned long long bestKey = 0ull;
        #pragma unroll
        for (int j = 0; j < 4; ++j) {
            float p0, p1;
            unpack2(acc[i][j], p0, p1);
            int n0 = nBase + tx * 8 + j * 2;
            // dist = fl( fl(r + c) - 2*p )   (2*p exact; fma = single rounding)
            float S0 = __fadd_rn(r, cn[j * 2]);
            float S1 = __fadd_rn(r, cn[j * 2 + 1]);
            float d0 = __fmaf_rn(-2.0f, p0, S0);
            float d1 = __fmaf_rn(-2.0f, p1, S1);
            // min dist; tie -> smallest index  (maximize packed key)
            unsigned long long k0 =
                ((unsigned long long)(~ordf(d0)) << 32) | (unsigned)(kcb - 1 - n0);
            unsigned long long k1 =
                ((unsigned long long)(~ordf(d1)) << 32) | (unsigned)(kcb - 2 - n0);
            if (k0 > bestKey) bestKey = k0;
            if (k1 > bestKey) bestKey = k1;
        }
        // reduce across the 16 tx lanes (lane = (ty&1)*16 + tx; xor<16 stays in group)
        #pragma unroll
        for (int off = 8; off; off >>= 1) {
            unsigned long long o = __shfl_xor_sync(0xFFFFFFFFu, bestKey, off);
            if (o > bestKey) bestKey = o;
        }
        if (tx == 0)
            atomicMax(&g_bestkey[mBase + ty * 16 + i], bestKey);
    }
}

// ---------------------------------------------------------------------------
// Gather winner; write quantized_st = z + fl(q - z) (reference-exact),
// index as f32, per-token squared error for the loss.
// ---------------------------------------------------------------------------
__global__ void vq_quantize_kernel(const float* __restrict__ Z,
                                   const float* __restrict__ CB,
                                   float* __restrict__ out,
                                   int kcb, int writeIdx, size_t idxOff) {
    int t = blockIdx.x;
    int tid = threadIdx.x;
    unsigned long long key = g_bestkey[t];
    int n = (kcb - 1) - (int)(unsigned)(key & 0xFFFFFFFFull);

    float4 q = reinterpret_cast<const float4*>(CB + (size_t)n * 512)[tid];
    float4 z = reinterpret_cast<const float4*>(Z + (size_t)t * 512)[tid];

    // straight-through value, elementwise fp32 exactly as reference
    float4 o;
    float dx = __fsub_rn(q.x, z.x);
    float dy = __fsub_rn(q.y, z.y);
    float dz = __fsub_rn(q.z, z.z);
    float dw = __fsub_rn(q.w, z.w);
    o.x = __fadd_rn(z.x, dx);
    o.y = __fadd_rn(z.y, dy);
    o.z = __fadd_rn(z.z, dz);
    o.w = __fadd_rn(z.w, dw);
    reinterpret_cast<float4*>(out)[(size_t)t * 128 + tid] = o;

    float s = dx * dx + dy * dy + dz * dz + dw * dw;
    #pragma unroll
    for (int off = 16; off; off >>= 1)
        s += __shfl_xor_sync(0xFFFFFFFFu, s, off);
    __shared__ float ws[4];
    if ((tid & 31) == 0) ws[tid >> 5] = s;
    __syncthreads();
    if (tid == 0) {
        g_tokensum[t] = ws[0] + ws[1] + ws[2] + ws[3];
        if (writeIdx) out[idxOff + t] = (float)n;
    }
}

// Deterministic loss reduction (no float atomics -> replay-identical output).
__global__ void vq_loss_kernel(float* __restrict__ out, size_t lossOff, int ntok) {
    __shared__ float sm[1024];
    int i = threadIdx.x;
    float s = 0.0f;
    for (int j = i; j < ntok; j += 1024) s += g_tokensum[j];
    sm[i] = s;
    __syncthreads();
    for (int st = 512; st; st >>= 1) {
        if (i < st) sm[i] += sm[i + st];
        __syncthreads();
    }
    if (i == 0)
        out[lossOff] = 1.25f * sm[0] / ((float)ntok * 512.0f);
}

// ---------------------------------------------------------------------------
extern "C" void kernel_launch(void* const* d_in, const int* in_sizes, int n_in,
                              void* d_out, int out_size) {
    const float* p0 = (const float*)d_in[0];
    const float* p1 = (const float*)d_in[1];
    int s0 = in_sizes[0], s1 = in_sizes[1];

    const float* Z  = p0;
    const float* CB = p1;
    int zN = s0, cN = s1;
    if (s1 > s0) { Z = p1; CB = p0; zN = s1; cN = s0; }

    const int ntok = zN / 512;   // 32768
    const int kcb  = cN / 512;   // 8192
    float* out = (float*)d_out;

    const size_t qElems = (size_t)ntok * 512;
    const int writeIdx  = ((size_t)out_size >= qElems + (size_t)ntok);
    const int writeLoss = ((size_t)out_size >= qElems + (size_t)ntok + 1);

    vq_init_kernel<<<(ntok + 1023) / 1024, 1024>>>(ntok);
    vq_rownorm_kernel<<<kcb, 128>>>(CB, 0);   // -> g_codenorm
    vq_rownorm_kernel<<<ntok, 128>>>(Z, 1);   // -> g_zn

    dim3 grid(kcb / BN, ntok / BM);  // (64, 256)
    vq_gemm_kernel<<<grid, 128>>>(Z, CB, kcb);

    vq_quantize_kernel<<<ntok, 128>>>(Z, CB, out, kcb, writeIdx, qElems);
    if (writeLoss)
        vq_loss_kernel<<<1, 1024>>>(out, qElems + (size_t)ntok, ntok);
}

// round 5
// speedup vs baseline: 1.0001x; 1.0001x over previous
#include <cuda_runtime.h>
#include <cuda_bf16.h>
#include <cstdint>

// ---------------------------------------------------------------------------
// VectorQuantize: z [32768,512] f32, codebook [8192,512] f32
// Reference semantics replicated exactly:
//   p    = z @ cb.T                       (fp32 accum)
//   dist = fl( fl(r_m + c_n) - 2*p )      (fp32, ULP(~512) grid => ties!)
//   idx  = argmin dist, first index on ties
//   out  = concat( z + fl(q - z) [N*512], idx as f32 [N], 1.25*mean((z-q)^2) )
// ---------------------------------------------------------------------------

#define NTOK_MAX 32768
#define KCB_MAX  8192

__device__ unsigned long long g_bestkey[NTOK_MAX];
__device__ float              g_codenorm[KCB_MAX];   // ||e_n||^2
__device__ float              g_zn[NTOK_MAX];        // ||z_m||^2
__device__ float              g_tokensum[NTOK_MAX];

// ---- packed f32x2 helpers --------------------------------------------------
__device__ __forceinline__ unsigned long long dup2(float x) {
    unsigned long long d;
    asm("mov.b64 %0, {%1, %1};" : "=l"(d) : "f"(x));
    return d;
}
__device__ __forceinline__ void fma2(unsigned long long& acc,
                                     unsigned long long a,
                                     unsigned long long b) {
    asm("fma.rn.f32x2 %0, %1, %2, %0;" : "+l"(acc) : "l"(a), "l"(b));
}
__device__ __forceinline__ void unpack2(unsigned long long v, float& lo, float& hi) {
    asm("mov.b64 {%0, %1}, %2;" : "=f"(lo), "=f"(hi) : "l"(v));
}
// order-preserving float -> uint map (monotone increasing)
__device__ __forceinline__ unsigned ordf(float f) {
    unsigned u = __float_as_uint(f);
    return (u & 0x80000000u) ? ~u : (u | 0x80000000u);
}

// ---------------------------------------------------------------------------
__global__ void vq_init_kernel(int ntok) {
    int i = blockIdx.x * blockDim.x + threadIdx.x;
    if (i < ntok) g_bestkey[i] = 0ull;
}

// row norm ||v||^2 into a __device__ global selected by `dest`
// (device globals must NOT be passed as kernel args from host code).
__global__ void vq_rownorm_kernel(const float* __restrict__ X, int dest) {
    int c = blockIdx.x;
    int t = threadIdx.x;
    float4 v = reinterpret_cast<const float4*>(X + (size_t)c * 512)[t];
    float s = v.x * v.x + v.y * v.y + v.z * v.z + v.w * v.w;
    #pragma unroll
    for (int off = 16; off; off >>= 1)
        s += __shfl_xor_sync(0xFFFFFFFFu, s, off);
    __shared__ float ws[4];
    if ((t & 31) == 0) ws[t >> 5] = s;
    __syncthreads();
    if (t == 0) {
        float r = ws[0] + ws[1] + ws[2] + ws[3];
        if (dest == 0) g_codenorm[c] = r;
        else           g_zn[c] = r;
    }
}

// ---------------------------------------------------------------------------
// Fused fp32 GEMM: 128x128 CTA tile, BK=16, 128 threads, 16x8 per-thread tile
// via f32x2 FMA. LDS per MAC cut 25% vs 8x8 (l1tex was the binding pipe).
// + reference-exact dist rounding + argmin(first-index ties) publish.
// ---------------------------------------------------------------------------
#define BM 128
#define BN 128
#define BK 16
#define TS 132   // padded row stride (floats)

__global__ __launch_bounds__(128, 2)
void vq_gemm_kernel(const float* __restrict__ Z, const float* __restrict__ CB,
                    int kcb) {
    __shared__ float As[2][BK * TS];   // [k][m]
    __shared__ float Bs[2][BK * TS];   // [k][n]

    const int tid = threadIdx.x;
    const int tx = tid & 15;      // n-thread: 16 x 8 cols = 128
    const int ty = tid >> 4;      // m-thread: 8 x 16 rows = 128
    const int mBase = blockIdx.y * BM;
    const int nBase = blockIdx.x * BN;

    // global loaders: thread tid owns full k-slab of row `tid` (A and B)
    const float* Ap = Z  + (size_t)(mBase + tid) * 512;
    const float* Bp = CB + (size_t)(nBase + tid) * 512;

    float4 ra[4], rb[4];
    #pragma unroll
    for (int j = 0; j < 4; ++j) {
        ra[j] = *reinterpret_cast<const float4*>(Ap + j * 4);
        rb[j] = *reinterpret_cast<const float4*>(Bp + j * 4);
    }

    unsigned long long acc[16][4];
    #pragma unroll
    for (int i = 0; i < 16; ++i)
        #pragma unroll
        for (int j = 0; j < 4; ++j) acc[i][j] = 0ull;

    // store first tile transposed
    #pragma unroll
    for (int j = 0; j < 4; ++j) {
        As[0][(j * 4 + 0) * TS + tid] = ra[j].x;
        As[0][(j * 4 + 1) * TS + tid] = ra[j].y;
        As[0][(j * 4 + 2) * TS + tid] = ra[j].z;
        As[0][(j * 4 + 3) * TS + tid] = ra[j].w;
        Bs[0][(j * 4 + 0) * TS + tid] = rb[j].x;
        Bs[0][(j * 4 + 1) * TS + tid] = rb[j].y;
        Bs[0][(j * 4 + 2) * TS + tid] = rb[j].z;
        Bs[0][(j * 4 + 3) * TS + tid] = rb[j].w;
    }
    __syncthreads();

    int buf = 0;
    const int NK = 512 / BK;  // 32
    for (int t = 0; t < NK; ++t) {
        if (t + 1 < NK) {
            Ap += BK; Bp += BK;
            #pragma unroll
            for (int j = 0; j < 4; ++j) {
                ra[j] = *reinterpret_cast<const float4*>(Ap + j * 4);
                rb[j] = *reinterpret_cast<const float4*>(Bp + j * 4);
            }
        }

        #pragma unroll
        for (int k = 0; k < BK; ++k) {
            const float* ap = &As[buf][k * TS + ty * 16];
            float4 av0 = *reinterpret_cast<const float4*>(ap);
            float4 av1 = *reinterpret_cast<const float4*>(ap + 4);
            float4 av2 = *reinterpret_cast<const float4*>(ap + 8);
            float4 av3 = *reinterpret_cast<const float4*>(ap + 12);
            const float* bp_ = &Bs[buf][k * TS + tx * 8];
            ulonglong2 bv0 = *reinterpret_cast<const ulonglong2*>(bp_);
            ulonglong2 bv1 = *reinterpret_cast<const ulonglong2*>(bp_ + 4);
            unsigned long long bp[4] = {bv0.x, bv0.y, bv1.x, bv1.y};
            float af[16] = {av0.x, av0.y, av0.z, av0.w,
                            av1.x, av1.y, av1.z, av1.w,
                            av2.x, av2.y, av2.z, av2.w,
                            av3.x, av3.y, av3.z, av3.w};
            #pragma unroll
            for (int i = 0; i < 16; ++i) {
                unsigned long long da = dup2(af[i]);
                fma2(acc[i][0], da, bp[0]);
                fma2(acc[i][1], da, bp[1]);
                fma2(acc[i][2], da, bp[2]);
                fma2(acc[i][3], da, bp[3]);
            }
        }

        if (t + 1 < NK) {
            int nb = buf ^ 1;
            #pragma unroll
            for (int j = 0; j < 4; ++j) {
                As[nb][(j * 4 + 0) * TS + tid] = ra[j].x;
                As[nb][(j * 4 + 1) * TS + tid] = ra[j].y;
                As[nb][(j * 4 + 2) * TS + tid] = ra[j].z;
                As[nb][(j * 4 + 3) * TS + tid] = ra[j].w;
                Bs[nb][(j * 4 + 0) * TS + tid] = rb[j].x;
                Bs[nb][(j * 4 + 1) * TS + tid] = rb[j].y;
                Bs[nb][(j * 4 + 2) * TS + tid] = rb[j].z;
                Bs[nb][(j * 4 + 3) * TS + tid] = rb[j].w;
            }
        }
        __syncthreads();
        buf ^= 1;
    }

    // ---- epilogue: reference-exact dist rounding, argmin, publish ---------
    float cn[8];
    #pragma unroll
    for (int j = 0; j < 8; ++j) cn[j] = g_codenorm[nBase + tx * 8 + j];

    #pragma unroll
    for (int i = 0; i < 16; ++i) {
        const float r = g_zn[mBase + ty * 16 + i];
        unsigned long long bestKey = 0ull;
        #pragma unroll
        for (int j = 0; j < 4; ++j) {
            float p0, p1;
            unpack2(acc[i][j], p0, p1);
            int n0 = nBase + tx * 8 + j * 2;
            // dist = fl( fl(r + c) - 2*p )   (2*p exact; fma = single rounding)
            float S0 = __fadd_rn(r, cn[j * 2]);
            float S1 = __fadd_rn(r, cn[j * 2 + 1]);
            float d0 = __fmaf_rn(-2.0f, p0, S0);
            float d1 = __fmaf_rn(-2.0f, p1, S1);
            // min dist; tie -> smallest index  (maximize packed key)
            unsigned long long k0 =
                ((unsigned long long)(~ordf(d0)) << 32) | (unsigned)(kcb - 1 - n0);
            unsigned long long k1 =
                ((unsigned long long)(~ordf(d1)) << 32) | (unsigned)(kcb - 2 - n0);
            if (k0 > bestKey) bestKey = k0;
            if (k1 > bestKey) bestKey = k1;
        }
        // reduce across the 16 tx lanes (lane = (ty&1)*16 + tx; xor<16 stays in group)
        #pragma unroll
        for (int off = 8; off; off >>= 1) {
            unsigned long long o = __shfl_xor_sync(0xFFFFFFFFu, bestKey, off);
            if (o > bestKey) bestKey = o;
        }
        if (tx == 0)
            atomicMax(&g_bestkey[mBase + ty * 16 + i], bestKey);
    }
}

// ---------------------------------------------------------------------------
// Gather winner; write quantized_st = z + fl(q - z) (reference-exact),
// index as f32, per-token squared error for the loss.
// ---------------------------------------------------------------------------
__global__ void vq_quantize_kernel(const float* __restrict__ Z,
                                   const float* __restrict__ CB,
                                   float* __restrict__ out,
                                   int kcb, int writeIdx, size_t idxOff) {
    int t = blockIdx.x;
    int tid = threadIdx.x;
    unsigned long long key = g_bestkey[t];
    int n = (kcb - 1) - (int)(unsigned)(key & 0xFFFFFFFFull);

    float4 q = reinterpret_cast<const float4*>(CB + (size_t)n * 512)[tid];
    float4 z = reinterpret_cast<const float4*>(Z + (size_t)t * 512)[tid];

    // straight-through value, elementwise fp32 exactly as reference
    float4 o;
    float dx = __fsub_rn(q.x, z.x);
    float dy = __fsub_rn(q.y, z.y);
    float dz = __fsub_rn(q.z, z.z);
    float dw = __fsub_rn(q.w, z.w);
    o.x = __fadd_rn(z.x, dx);
    o.y = __fadd_rn(z.y, dy);
    o.z = __fadd_rn(z.z, dz);
    o.w = __fadd_rn(z.w, dw);
    reinterpret_cast<float4*>(out)[(size_t)t * 128 + tid] = o;

    float s = dx * dx + dy * dy + dz * dz + dw * dw;
    #pragma unroll
    for (int off = 16; off; off >>= 1)
        s += __shfl_xor_sync(0xFFFFFFFFu, s, off);
    __shared__ float ws[4];
    if ((tid & 31) == 0) ws[tid >> 5] = s;
    __syncthreads();
    if (tid == 0) {
        g_tokensum[t] = ws[0] + ws[1] + ws[2] + ws[3];
        if (writeIdx) out[idxOff + t] = (float)n;
    }
}

// Deterministic loss reduction (no float atomics -> replay-identical output).
__global__ void vq_loss_kernel(float* __restrict__ out, size_t lossOff, int ntok) {
    __shared__ float sm[1024];
    int i = threadIdx.x;
    float s = 0.0f;
    for (int j = i; j < ntok; j += 1024) s += g_tokensum[j];
    sm[i] = s;
    __syncthreads();
    for (int st = 512; st; st >>= 1) {
        if (i < st) sm[i] += sm[i + st];
        __syncthreads();
    }
    if (i == 0)
        out[lossOff] = 1.25f * sm[0] / ((float)ntok * 512.0f);
}

// ---------------------------------------------------------------------------
extern "C" void kernel_launch(void* const* d_in, const int* in_sizes, int n_in,
                              void* d_out, int out_size) {
    const float* p0 = (const float*)d_in[0];
    const float* p1 = (const float*)d_in[1];
    int s0 = in_sizes[0], s1 = in_sizes[1];

    const float* Z  = p0;
    const float* CB = p1;
    int zN = s0, cN = s1;
    if (s1 > s0) { Z = p1; CB = p0; zN = s1; cN = s0; }

    const int ntok = zN / 512;   // 32768
    const int kcb  = cN / 512;   // 8192
    float* out = (float*)d_out;

    const size_t qElems = (size_t)ntok * 512;
    const int writeIdx  = ((size_t)out_size >= qElems + (size_t)ntok);
    const int writeLoss = ((size_t)out_size >= qElems + (size_t)ntok + 1);

    vq_init_kernel<<<(ntok + 1023) / 1024, 1024>>>(ntok);
    vq_rownorm_kernel<<<kcb, 128>>>(CB, 0);   // -> g_codenorm
    vq_rownorm_kernel<<<ntok, 128>>>(Z, 1);   // -> g_zn

    dim3 grid(kcb / BN, ntok / BM);  // (64, 256)
    vq_gemm_kernel<<<grid, 128>>>(Z, CB, kcb);

    vq_quantize_kernel<<<ntok, 128>>>(Z, CB, out, kcb, writeIdx, qElems);
    if (writeLoss)
        vq_loss_kernel<<<1, 1024>>>(out, qElems + (size_t)ntok, ntok);
}

// round 9
// speedup vs baseline: 3.5175x; 3.5170x over previous
#include <cuda_runtime.h>
#include <cuda_bf16.h>
#include <cstdint>

// ===========================================================================
// VectorQuantize, two-phase (mma.sync bf16 HMMA — arch-agnostic, no tcgen05):
//   Phase 1: bf16 m16n8k16 GEMM -> approx per-(token, 128-code tile) min dist
//   Phase 2: exact fp32 rescoring of candidate tiles, bit-identical to the
//            round-3 passing kernel (grid-exact dist + first-index ties)
// ===========================================================================

#define NTOK 32768
#define KCB  8192
#define NTILES 64
#define CAP  4096
#define DELTA 1e-3f

__device__ unsigned long long g_bestkey[NTOK];
__device__ float              g_codenorm[KCB];
__device__ float              g_zn[NTOK];
__device__ float              g_tokensum[NTOK];
__device__ __nv_bfloat16      g_zbf[NTOK * 512];
__device__ __nv_bfloat16      g_cbbf[KCB * 512];
__device__ float              g_tilebest[NTOK * NTILES];
__device__ int                g_tilecount[NTILES];
__device__ int                g_tilelist[NTILES * CAP];

// order-preserving float <-> uint maps
__device__ __forceinline__ unsigned ordf(float f) {
    unsigned u = __float_as_uint(f);
    return (u & 0x80000000u) ? ~u : (u | 0x80000000u);
}
__device__ __forceinline__ float iordf(unsigned u) {
    unsigned v = (u & 0x80000000u) ? (u & 0x7FFFFFFFu) : ~u;
    return __uint_as_float(v);
}
__device__ __forceinline__ uint32_t smem_u32(const void* p) {
    uint32_t a;
    asm("{ .reg .u64 t; cvta.to.shared.u64 t, %1; cvt.u32.u64 %0, t; }"
        : "=r"(a) : "l"(p));
    return a;
}
__device__ __forceinline__ void ldmatrix_x4(uint32_t& r0, uint32_t& r1,
                                            uint32_t& r2, uint32_t& r3,
                                            uint32_t addr) {
    asm volatile("ldmatrix.sync.aligned.m8n8.x4.shared.b16 {%0,%1,%2,%3}, [%4];"
                 : "=r"(r0), "=r"(r1), "=r"(r2), "=r"(r3) : "r"(addr));
}
__device__ __forceinline__ void mma_bf16(float& c0, float& c1, float& c2, float& c3,
                                         uint32_t a0, uint32_t a1, uint32_t a2,
                                         uint32_t a3, uint32_t b0, uint32_t b1) {
    asm volatile(
        "mma.sync.aligned.m16n8k16.row.col.f32.bf16.bf16.f32 "
        "{%0,%1,%2,%3}, {%4,%5,%6,%7}, {%8,%9}, {%0,%1,%2,%3};"
        : "+f"(c0), "+f"(c1), "+f"(c2), "+f"(c3)
        : "r"(a0), "r"(a1), "r"(a2), "r"(a3), "r"(b0), "r"(b1));
}

// ---------------------------------------------------------------------------
__global__ void vq_init_kernel(int ntok) {
    int i = blockIdx.x * blockDim.x + threadIdx.x;
    if (i < ntok) g_bestkey[i] = 0ull;
    if (i < NTILES) g_tilecount[i] = 0;
}

__global__ void vq_rownorm_kernel(const float* __restrict__ X, int dest) {
    int c = blockIdx.x;
    int t = threadIdx.x;
    float4 v = reinterpret_cast<const float4*>(X + (size_t)c * 512)[t];
    float s = v.x * v.x + v.y * v.y + v.z * v.z + v.w * v.w;
    #pragma unroll
    for (int off = 16; off; off >>= 1)
        s += __shfl_xor_sync(0xFFFFFFFFu, s, off);
    __shared__ float ws[4];
    if ((t & 31) == 0) ws[t >> 5] = s;
    __syncthreads();
    if (t == 0) {
        float r = ws[0] + ws[1] + ws[2] + ws[3];
        if (dest == 0) g_codenorm[c] = r;
        else           g_zn[c] = r;
    }
}

__global__ void vq_tobf16_kernel(const float* __restrict__ src, int n, int which) {
    int i = (blockIdx.x * blockDim.x + threadIdx.x) * 8;
    if (i >= n) return;
    float4 a = *reinterpret_cast<const float4*>(src + i);
    float4 b = *reinterpret_cast<const float4*>(src + i + 4);
    __nv_bfloat16 v[8] = {
        __float2bfloat16_rn(a.x), __float2bfloat16_rn(a.y),
        __float2bfloat16_rn(a.z), __float2bfloat16_rn(a.w),
        __float2bfloat16_rn(b.x), __float2bfloat16_rn(b.y),
        __float2bfloat16_rn(b.z), __float2bfloat16_rn(b.w)};
    __nv_bfloat16* dst = which ? g_zbf : g_cbbf;
    *reinterpret_cast<uint4*>(dst + i) = *reinterpret_cast<uint4*>(v);
}

// ---------------------------------------------------------------------------
// Phase 1: bf16 mma.sync GEMM. CTA 128(tok) x 128(code), BK=32, 256 thr,
// 8 warps in 4(m) x 2(n), warp tile 32x64. Double-buffered smem (pad 40).
// Epilogue: per token-row min of fl(cn - 2p) over the 128-code tile.
// ---------------------------------------------------------------------------
#define P1_STRIDE 40   // bf16 elems per smem row (32 data + 8 pad)

__global__ __launch_bounds__(256, 2)
void vq_phase1_kernel() {
    __shared__ __nv_bfloat16 As[2][128 * P1_STRIDE];
    __shared__ __nv_bfloat16 Bs[2][128 * P1_STRIDE];
    __shared__ unsigned smin[128];

    const int tid = threadIdx.x;
    const int lane = tid & 31;
    const int wid = tid >> 5;
    const int wm = wid & 3;        // 4 m-blocks of 32
    const int wn = wid >> 2;       // 2 n-blocks of 64
    const int mBase = blockIdx.y * 128;
    const int nBase = blockIdx.x * 128;

    if (tid < 128) smin[tid] = 0xFFFFFFFFu;

    // global loader: thread t owns row t>>1, col-granules (t&1)*2 + {0,1}
    const int grow = tid >> 1;
    const int gcg  = (tid & 1) * 2;
    const __nv_bfloat16* Ag = g_zbf  + (size_t)(mBase + grow) * 512 + gcg * 8;
    const __nv_bfloat16* Bg = g_cbbf + (size_t)(nBase + grow) * 512 + gcg * 8;

    uint4 va0 = *reinterpret_cast<const uint4*>(Ag);
    uint4 va1 = *reinterpret_cast<const uint4*>(Ag + 8);
    uint4 vb0 = *reinterpret_cast<const uint4*>(Bg);
    uint4 vb1 = *reinterpret_cast<const uint4*>(Bg + 8);

    float acc[2][8][4];
    #pragma unroll
    for (int mb = 0; mb < 2; ++mb)
        #pragma unroll
        for (int nb = 0; nb < 8; ++nb)
            #pragma unroll
            for (int r = 0; r < 4; ++r) acc[mb][nb][r] = 0.0f;

    // smem byte addresses for ldmatrix
    const uint32_t asb = smem_u32(&As[0][0]);
    const uint32_t bsb = smem_u32(&Bs[0][0]);
    const uint32_t bufBytes = 128 * P1_STRIDE * 2;

    {   // store first tile
        __nv_bfloat16* pa = &As[0][grow * P1_STRIDE + gcg * 8];
        __nv_bfloat16* pb = &Bs[0][grow * P1_STRIDE + gcg * 8];
        *reinterpret_cast<uint4*>(pa)     = va0;
        *reinterpret_cast<uint4*>(pa + 8) = va1;
        *reinterpret_cast<uint4*>(pb)     = vb0;
        *reinterpret_cast<uint4*>(pb + 8) = vb1;
    }
    __syncthreads();

    const int NK = 512 / 32;   // 16
    for (int t = 0; t < NK; ++t) {
        const int buf = t & 1;
        if (t + 1 < NK) {
            Ag += 32; Bg += 32;
            va0 = *reinterpret_cast<const uint4*>(Ag);
            va1 = *reinterpret_cast<const uint4*>(Ag + 8);
            vb0 = *reinterpret_cast<const uint4*>(Bg);
            vb1 = *reinterpret_cast<const uint4*>(Bg + 8);
        }

        #pragma unroll
        for (int kk = 0; kk < 32; kk += 16) {
            // A fragments for both m16 blocks
            uint32_t a[2][4];
            #pragma unroll
            for (int mb = 0; mb < 2; ++mb) {
                int arow = wm * 32 + mb * 16 + (lane & 15);
                int acol = kk + ((lane & 16) ? 8 : 0);
                uint32_t addr = asb + buf * bufBytes +
                                (uint32_t)(arow * P1_STRIDE + acol) * 2;
                ldmatrix_x4(a[mb][0], a[mb][1], a[mb][2], a[mb][3], addr);
            }
            // B: 4 x (16n x 16k) loads, 4 mma each
            #pragma unroll
            for (int nb2 = 0; nb2 < 4; ++nb2) {
                int brow = wn * 64 + nb2 * 16 + (lane & 7) + ((lane & 16) ? 8 : 0);
                int bcol = kk + ((lane & 8) ? 8 : 0);
                uint32_t addr = bsb + buf * bufBytes +
                                (uint32_t)(brow * P1_STRIDE + bcol) * 2;
                uint32_t b0, b1, b2, b3;
                ldmatrix_x4(b0, b1, b2, b3, addr);
                #pragma unroll
                for (int mb = 0; mb < 2; ++mb) {
                    float* c0 = acc[mb][nb2 * 2];
                    mma_bf16(c0[0], c0[1], c0[2], c0[3],
                             a[mb][0], a[mb][1], a[mb][2], a[mb][3], b0, b1);
                    float* c1 = acc[mb][nb2 * 2 + 1];
                    mma_bf16(c1[0], c1[1], c1[2], c1[3],
                             a[mb][0], a[mb][1], a[mb][2], a[mb][3], b2, b3);
                }
            }
        }

        if (t + 1 < NK) {
            int nb = buf ^ 1;
            __nv_bfloat16* pa = &As[nb][grow * P1_STRIDE + gcg * 8];
            __nv_bfloat16* pb = &Bs[nb][grow * P1_STRIDE + gcg * 8];
            *reinterpret_cast<uint4*>(pa)     = va0;
            *reinterpret_cast<uint4*>(pa + 8) = va1;
            *reinterpret_cast<uint4*>(pb)     = vb0;
            *reinterpret_cast<uint4*>(pb + 8) = vb1;
        }
        __syncthreads();
    }

    // ---- epilogue: approx dist, per-row tile-min ---------------------------
    float cn[16];
    #pragma unroll
    for (int nb = 0; nb < 8; ++nb) {
        int col = nBase + wn * 64 + nb * 8 + 2 * (lane & 3);
        cn[nb * 2]     = g_codenorm[col];
        cn[nb * 2 + 1] = g_codenorm[col + 1];
    }

    #pragma unroll
    for (int mb = 0; mb < 2; ++mb) {
        float m0 = 3.4e38f, m1 = 3.4e38f;
        #pragma unroll
        for (int nb = 0; nb < 8; ++nb) {
            m0 = fminf(m0, __fmaf_rn(-2.0f, acc[mb][nb][0], cn[nb * 2]));
            m0 = fminf(m0, __fmaf_rn(-2.0f, acc[mb][nb][1], cn[nb * 2 + 1]));
            m1 = fminf(m1, __fmaf_rn(-2.0f, acc[mb][nb][2], cn[nb * 2]));
            m1 = fminf(m1, __fmaf_rn(-2.0f, acc[mb][nb][3], cn[nb * 2 + 1]));
        }
        // quad-reduce (lanes sharing the same row differ in lane&3)
        #pragma unroll
        for (int off = 1; off < 4; off <<= 1) {
            m0 = fminf(m0, __shfl_xor_sync(0xFFFFFFFFu, m0, off));
            m1 = fminf(m1, __shfl_xor_sync(0xFFFFFFFFu, m1, off));
        }
        if ((lane & 3) == 0) {
            int r = wm * 32 + mb * 16 + (lane >> 2);
            atomicMin(&smin[r], ordf(m0));
            atomicMin(&smin[r + 8], ordf(m1));
        }
    }
    __syncthreads();
    if (tid < 128)
        g_tilebest[(size_t)(mBase + tid) * NTILES + blockIdx.x] = iordf(smin[tid]);
}

// ---------------------------------------------------------------------------
// Candidate selection: one warp per token.
// ---------------------------------------------------------------------------
__global__ void vq_candidates_kernel(int ntok) {
    int warp = (blockIdx.x * blockDim.x + threadIdx.x) >> 5;
    int lane = threadIdx.x & 31;
    if (warp >= ntok) return;
    const float* tb = g_tilebest + (size_t)warp * NTILES;
    float a = tb[lane];
    float b = tb[lane + 32];
    float m = fminf(a, b);
    #pragma unroll
    for (int off = 16; off; off >>= 1)
        m = fminf(m, __shfl_xor_sync(0xFFFFFFFFu, m, off));
    float thr = m + DELTA;
    if (a <= thr) {
        int p = atomicAdd(&g_tilecount[lane], 1);
        if (p < CAP) g_tilelist[lane * CAP + p] = warp;
    }
    if (b <= thr) {
        int p = atomicAdd(&g_tilecount[lane + 32], 1);
        if (p < CAP) g_tilelist[(lane + 32) * CAP + p] = warp;
    }
}

// ---------------------------------------------------------------------------
// Phase 2: exact fp32 rescoring (bit-identical chains to the round-3 kernel).
// ---------------------------------------------------------------------------
__global__ __launch_bounds__(256)
void vq_phase2_kernel(const float* __restrict__ Z, const float* __restrict__ CB,
                      int kcb) {
    const int tile = blockIdx.y;
    const int part = blockIdx.x;
    int cnt = g_tilecount[tile];
    if (cnt > CAP) cnt = CAP;
    const int base = part * 128;
    if (base >= cnt) return;

    __shared__ float zs[32][132];
    __shared__ float cs[32][132];
    __shared__ int   toks[128];

    const int tid = threadIdx.x;
    const int tx = tid & 15;
    const int ty = tid >> 4;

    if (tid < 128)
        toks[tid] = (base + tid < cnt) ? g_tilelist[tile * CAP + base + tid] : -1;
    __syncthreads();

    float acc[8][8];
    #pragma unroll
    for (int i = 0; i < 8; ++i)
        #pragma unroll
        for (int j = 0; j < 8; ++j) acc[i][j] = 0.0f;

    const int row = tid >> 1;
    const int half = tid & 1;
    const int tokR = toks[row] < 0 ? 0 : toks[row];
    const int codeR = tile * 128 + row;

    for (int k0 = 0; k0 < 512; k0 += 32) {
        const float* zp = Z  + (size_t)tokR * 512 + k0 + half * 16;
        const float* cp = CB + (size_t)codeR * 512 + k0 + half * 16;
        #pragma unroll
        for (int q = 0; q < 4; ++q) {
            float4 vz = *reinterpret_cast<const float4*>(zp + q * 4);
            float4 vc = *reinterpret_cast<const float4*>(cp + q * 4);
            int kk = half * 16 + q * 4;
            zs[kk + 0][row] = vz.x; zs[kk + 1][row] = vz.y;
            zs[kk + 2][row] = vz.z; zs[kk + 3][row] = vz.w;
            cs[kk + 0][row] = vc.x; cs[kk + 1][row] = vc.y;
            cs[kk + 2][row] = vc.z; cs[kk + 3][row] = vc.w;
        }
        __syncthreads();

        #pragma unroll
        for (int k = 0; k < 32; ++k) {
            const float* ap = &zs[k][ty * 8];
            float4 a0 = *reinterpret_cast<const float4*>(ap);
            float4 a1 = *reinterpret_cast<const float4*>(ap + 4);
            const float* bp = &cs[k][tx * 8];
            float4 b0 = *reinterpret_cast<const float4*>(bp);
            float4 b1 = *reinterpret_cast<const float4*>(bp + 4);
            float av[8] = {a0.x, a0.y, a0.z, a0.w, a1.x, a1.y, a1.z, a1.w};
            float bv[8] = {b0.x, b0.y, b0.z, b0.w, b1.x, b1.y, b1.z, b1.w};
            #pragma unroll
            for (int i = 0; i < 8; ++i)
                #pragma unroll
                for (int j = 0; j < 8; ++j)
                    acc[i][j] = __fmaf_rn(av[i], bv[j], acc[i][j]);
        }
        __syncthreads();
    }

    float cn[8];
    #pragma unroll
    for (int j = 0; j < 8; ++j) cn[j] = g_codenorm[tile * 128 + tx * 8 + j];

    #pragma unroll
    for (int i = 0; i < 8; ++i) {
        const int trow = ty * 8 + i;
        const int tok = toks[trow];
        const float r = (tok >= 0) ? g_zn[tok] : 0.0f;
        unsigned long long bestKey = 0ull;
        #pragma unroll
        for (int j = 0; j < 8; ++j) {
            int n = tile * 128 + tx * 8 + j;
            float S = __fadd_rn(r, cn[j]);
            float d = __fmaf_rn(-2.0f, acc[i][j], S);
            unsigned long long k =
                ((unsigned long long)(~ordf(d)) << 32) | (unsigned)(kcb - 1 - n);
            if (k > bestKey) bestKey = k;
        }
        #pragma unroll
        for (int off = 8; off; off >>= 1) {
            unsigned long long o = __shfl_xor_sync(0xFFFFFFFFu, bestKey, off);
            if (o > bestKey) bestKey = o;
        }
        if (tx == 0 && tok >= 0)
            atomicMax(&g_bestkey[tok], bestKey);
    }
}

// ---------------------------------------------------------------------------
__global__ void vq_quantize_kernel(const float* __restrict__ Z,
                                   const float* __restrict__ CB,
                                   float* __restrict__ out,
                                   int kcb, int writeIdx, size_t idxOff) {
    int t = blockIdx.x;
    int tid = threadIdx.x;
    unsigned long long key = g_bestkey[t];
    int n = (kcb - 1) - (int)(unsigned)(key & 0xFFFFFFFFull);

    float4 q = reinterpret_cast<const float4*>(CB + (size_t)n * 512)[tid];
    float4 z = reinterpret_cast<const float4*>(Z + (size_t)t * 512)[tid];

    float4 o;
    float dx = __fsub_rn(q.x, z.x);
    float dy = __fsub_rn(q.y, z.y);
    float dz = __fsub_rn(q.z, z.z);
    float dw = __fsub_rn(q.w, z.w);
    o.x = __fadd_rn(z.x, dx);
    o.y = __fadd_rn(z.y, dy);
    o.z = __fadd_rn(z.z, dz);
    o.w = __fadd_rn(z.w, dw);
    reinterpret_cast<float4*>(out)[(size_t)t * 128 + tid] = o;

    float s = dx * dx + dy * dy + dz * dz + dw * dw;
    #pragma unroll
    for (int off = 16; off; off >>= 1)
        s += __shfl_xor_sync(0xFFFFFFFFu, s, off);
    __shared__ float ws[4];
    if ((tid & 31) == 0) ws[tid >> 5] = s;
    __syncthreads();
    if (tid == 0) {
        g_tokensum[t] = ws[0] + ws[1] + ws[2] + ws[3];
        if (writeIdx) out[idxOff + t] = (float)n;
    }
}

__global__ void vq_loss_kernel(float* __restrict__ out, size_t lossOff, int ntok) {
    __shared__ float sm[1024];
    int i = threadIdx.x;
    float s = 0.0f;
    for (int j = i; j < ntok; j += 1024) s += g_tokensum[j];
    sm[i] = s;
    __syncthreads();
    for (int st = 512; st; st >>= 1) {
        if (i < st) sm[i] += sm[i + st];
        __syncthreads();
    }
    if (i == 0)
        out[lossOff] = 1.25f * sm[0] / ((float)ntok * 512.0f);
}

// ---------------------------------------------------------------------------
extern "C" void kernel_launch(void* const* d_in, const int* in_sizes, int n_in,
                              void* d_out, int out_size) {
    const float* p0 = (const float*)d_in[0];
    const float* p1 = (const float*)d_in[1];
    int s0 = in_sizes[0], s1 = in_sizes[1];

    const float* Z  = p0;
    const float* CB = p1;
    int zN = s0, cN = s1;
    if (s1 > s0) { Z = p1; CB = p0; zN = s1; cN = s0; }

    const int ntok = zN / 512;   // 32768
    const int kcb  = cN / 512;   // 8192
    float* out = (float*)d_out;

    const size_t qElems = (size_t)ntok * 512;
    const int writeIdx  = ((size_t)out_size >= qElems + (size_t)ntok);
    const int writeLoss = ((size_t)out_size >= qElems + (size_t)ntok + 1);

    vq_init_kernel<<<(ntok + 1023) / 1024, 1024>>>(ntok);
    vq_rownorm_kernel<<<kcb, 128>>>(CB, 0);   // -> g_codenorm
    vq_rownorm_kernel<<<ntok, 128>>>(Z, 1);   // -> g_zn
    vq_tobf16_kernel<<<(zN / 8 + 255) / 256, 256>>>(Z, zN, 1);
    vq_tobf16_kernel<<<(cN / 8 + 255) / 256, 256>>>(CB, cN, 0);

    dim3 g1(kcb / 128, ntok / 128);           // (64, 256)
    vq_phase1_kernel<<<g1, 256>>>();

    vq_candidates_kernel<<<(ntok * 32 + 255) / 256, 256>>>(ntok);

    dim3 g2(CAP / 128, NTILES);               // (32, 64)
    vq_phase2_kernel<<<g2, 256>>>(Z, CB, kcb);

    vq_quantize_kernel<<<ntok, 128>>>(Z, CB, out, kcb, writeIdx, qElems);
    if (writeLoss)
        vq_loss_kernel<<<1, 1024>>>(out, qElems + (size_t)ntok, ntok);
}